// round 10
// baseline (speedup 1.0000x reference)
#include <cuda_runtime.h>
#include <cstdint>

#define TT 512
#define BB 64
#define II 256
#define HH 512

// 64MB scratch for the precomputed input contribution xw[t][b][h]
__device__ float g_xw[TT * BB * HH];

// ---------------------------------------------------------------------------
// Phase 1: g_xw[m][h] = sum_i x[m][i] * W_ih[h][i] + b_ih[h] + b_hh[h]
//   64x64 tiles, BK=32, 256 threads, 4x4 per thread.
//   SMEM tiles stored TRANSPOSED (aT[k][m], wT[k][n]) so the inner-loop
//   LDS.128 reads are 16-distinct contiguous float4 (2-phase, conflict-free)
//   instead of the old 8-way-conflicted row-major reads.
// ---------------------------------------------------------------------------
__global__ __launch_bounds__(256, 2) void phase1_kernel(
    const float* __restrict__ A,
    const float* __restrict__ W,
    const float* __restrict__ bih,
    const float* __restrict__ bhh)
{
    __shared__ float aT[32][68];
    __shared__ float wT[32][68];

    const int tid = threadIdx.x;
    const int m0 = blockIdx.x * 64;
    const int n0 = blockIdx.y * 64;
    const int r0 = (tid & 15) * 4;
    const int c0 = (tid >> 4) * 4;

    float acc[4][4] = {};

    for (int k0 = 0; k0 < II; k0 += 32) {
        #pragma unroll
        for (int i = 0; i < 2; i++) {
            int idx = tid + i * 256;          // 0..511
            int row = idx >> 3;               // 0..63
            int kc  = (idx & 7) * 4;          // 0..28
            float4 av = *(const float4*)&A[(size_t)(m0 + row) * II + k0 + kc];
            aT[kc + 0][row] = av.x;
            aT[kc + 1][row] = av.y;
            aT[kc + 2][row] = av.z;
            aT[kc + 3][row] = av.w;
            float4 wv = *(const float4*)&W[(size_t)(n0 + row) * II + k0 + kc];
            wT[kc + 0][row] = wv.x;
            wT[kc + 1][row] = wv.y;
            wT[kc + 2][row] = wv.z;
            wT[kc + 3][row] = wv.w;
        }
        __syncthreads();

        #pragma unroll
        for (int k = 0; k < 32; k++) {
            float4 a4 = *(float4*)&aT[k][r0];
            float4 w4 = *(float4*)&wT[k][c0];
            float av[4] = {a4.x, a4.y, a4.z, a4.w};
            float wv[4] = {w4.x, w4.y, w4.z, w4.w};
            #pragma unroll
            for (int i = 0; i < 4; i++)
                #pragma unroll
                for (int j = 0; j < 4; j++)
                    acc[i][j] += av[i] * wv[j];
        }
        __syncthreads();
    }

    float b0 = bih[n0 + c0 + 0] + bhh[n0 + c0 + 0];
    float b1 = bih[n0 + c0 + 1] + bhh[n0 + c0 + 1];
    float b2 = bih[n0 + c0 + 2] + bhh[n0 + c0 + 2];
    float b3 = bih[n0 + c0 + 3] + bhh[n0 + c0 + 3];
    #pragma unroll
    for (int i = 0; i < 4; i++) {
        float4 o;
        o.x = acc[i][0] + b0;
        o.y = acc[i][1] + b1;
        o.z = acc[i][2] + b2;
        o.w = acc[i][3] + b3;
        *(float4*)&g_xw[(size_t)(m0 + r0 + i) * HH + n0 + c0] = o;
    }
}

// ---------------------------------------------------------------------------
// DSMEM / mbarrier helpers (cluster scope)
// ---------------------------------------------------------------------------
__device__ __forceinline__ uint32_t smem_u32(const void* p) {
    uint32_t a;
    asm("{ .reg .u64 t; cvta.to.shared.u64 t, %1; cvt.u32.u64 %0, t; }"
        : "=r"(a) : "l"(p));
    return a;
}

__device__ __forceinline__ void mbar_init(uint32_t mbar, uint32_t count) {
    asm volatile("mbarrier.init.shared.b64 [%0], %1;" :: "r"(mbar), "r"(count) : "memory");
}

__device__ __forceinline__ void mbar_wait_cluster(uint32_t mbar, uint32_t parity) {
    asm volatile(
        "{\n\t"
        ".reg .pred P;\n\t"
        "LW_%=:\n\t"
        "mbarrier.try_wait.parity.acquire.cluster.shared::cta.b64 P, [%0], %1, 0x989680;\n\t"
        "@P bra LD_%=;\n\t"
        "bra LW_%=;\n\t"
        "LD_%=:\n\t"
        "}"
        :: "r"(mbar), "r"(parity) : "memory");
}

__device__ __forceinline__ uint32_t mapa_u32(uint32_t laddr, uint32_t rank) {
    uint32_t ra;
    asm("mapa.shared::cluster.u32 %0, %1, %2;" : "=r"(ra) : "r"(laddr), "r"(rank));
    return ra;
}

// Arrive at a pre-mapa'd remote mbarrier address.
__device__ __forceinline__ void mbar_arrive_pre(uint32_t raddr) {
    asm volatile("mbarrier.arrive.release.cluster.shared::cluster.b64 _, [%0];"
                 :: "r"(raddr) : "memory");
}

// 8-byte DSMEM store to a pre-mapa'd remote address.
__device__ __forceinline__ void st_cluster_b64(uint32_t addr, float a, float b) {
    uint64_t v = ((uint64_t)__float_as_uint(b) << 32) | (uint64_t)__float_as_uint(a);
    asm volatile("st.shared::cluster.b64 [%0], %1;" :: "r"(addr), "l"(v) : "memory");
}

// ---------------------------------------------------------------------------
// Phase 2: cluster scan with TWO interleaved batch streams.
//   16 clusters x 8 CTAs. Cluster cid owns batches [4cid, 4cid+4):
//     stream A = batches {4cid, 4cid+1}, stream B = {4cid+2, 4cid+3}.
//   CTA rank r owns hidden rows [64r, 64r+64); W slice row-major in SMEM.
//   Streams are independent recurrences: while A's DSMEM exchange is in
//   flight, B computes (and vice versa) -> exchange latency overlapped.
//   Per stream: k-split 2 (K=256/thread) + one shfl_xor(16) reduce.
//   Arrives: 8 per barrier only (tid<16 after fence+syncthreads).
//
// SMEM layout (floats):
//   [0, 33024)        w_s    [64][516]
//   [33024, 35088)    hbufA  [2 parity][2 b][516]
//   [35088, 37152)    hbufB  [2 parity][2 b][516]
//   [37152, 37288)    stageA [2][68]
//   [37288, 37424)    stageB [2][68]
//   byte 149696:      mbarriers A0,A1,B0,B1 (count=8 each)
// ---------------------------------------------------------------------------
#define SMF_W   0
#define SMF_HA  33024
#define SMF_HB  35088
#define SMF_SA  37152
#define SMF_SB  37288
#define SM_MB_BYTE 149696
#define SM_TOTAL_BYTES (SM_MB_BYTE + 32)

__global__ void __cluster_dims__(8, 1, 1) __launch_bounds__(256, 1)
scan_kernel(const float* __restrict__ Whh, float* __restrict__ out, int has_hfinal)
{
    extern __shared__ float sm[];
    float* w_s = sm + SMF_W;
    float* hA  = sm + SMF_HA;
    float* hB  = sm + SMF_HB;
    float* sA  = sm + SMF_SA;
    float* sB  = sm + SMF_SB;

    const uint32_t base = smem_u32(sm);
    const uint32_t mb = base + SM_MB_BYTE;

    const int tid  = threadIdx.x;
    const int lane = tid & 31;
    const int wrp  = tid >> 5;
    uint32_t r;
    asm("mov.u32 %0, %%cluster_ctarank;" : "=r"(r));
    const int my_r = (int)r;
    const int cid = blockIdx.x >> 3;
    const int b0 = cid * 4;
    const int h0 = my_r * 64;

    if (tid == 0) {
        mbar_init(mb + 0, 8);   // A parity 0
        mbar_init(mb + 8, 8);   // A parity 1
        mbar_init(mb + 16, 8);  // B parity 0
        mbar_init(mb + 24, 8);  // B parity 1
    }

    // Load W_hh rows [h0, h0+64) row-major into w_s (coalesced).
    #pragma unroll
    for (int i = 0; i < 32; i++) {
        int idx = tid + i * 256;
        int row = idx >> 7;
        int kq  = idx & 127;
        *(float4*)&w_s[row * 516 + kq * 4] =
            *(const float4*)&Whh[(size_t)(h0 + row) * HH + kq * 4];
    }
    __syncthreads();
    asm volatile("barrier.cluster.arrive.aligned;" ::: "memory");
    asm volatile("barrier.cluster.wait.aligned;" ::: "memory");

    // Compute role: warp covers 8 h x 2 b x 2 k-halves
    const int h_l = (wrp << 3) | (lane & 7);   // 0..63
    const int b_l = (lane >> 3) & 1;           // 0..1
    const int ks  = lane >> 4;                 // 0..1
    const bool keeper = (ks == 0);
    const float* wp = w_s + h_l * 516 + ks * 256;

    const size_t offA = (size_t)(b0 + b_l) * HH + h0 + h_l;
    const size_t offB = (size_t)(b0 + 2 + b_l) * HH + h0 + h_l;

    // Push role: warp w -> rank w; lane covers 16B of the 512B slice.
    const int p_b = lane >> 4;          // 0..1
    const int p_j = (lane & 15) * 4;    // 0..60
    uint32_t dA[2], dB[2];
    #pragma unroll
    for (int pn = 0; pn < 2; pn++) {
        dA[pn] = mapa_u32(base + (uint32_t)(SMF_HA + pn * 1032 + p_b * 516 + my_r * 64 + p_j) * 4u,
                          (uint32_t)wrp);
        dB[pn] = mapa_u32(base + (uint32_t)(SMF_HB + pn * 1032 + p_b * 516 + my_r * 64 + p_j) * 4u,
                          (uint32_t)wrp);
    }
    // Arrive role: tid<8 -> stream A barrier of rank tid; tid 8..15 -> stream B.
    uint32_t remBar[2] = {0u, 0u};
    if (tid < 8) {
        remBar[0] = mapa_u32(mb + 0, (uint32_t)tid);
        remBar[1] = mapa_u32(mb + 8, (uint32_t)tid);
    } else if (tid < 16) {
        remBar[0] = mapa_u32(mb + 16, (uint32_t)(tid - 8));
        remBar[1] = mapa_u32(mb + 24, (uint32_t)(tid - 8));
    }

    int phA[2] = {0, 0}, phB[2] = {0, 0};
    float xwA = keeper ? g_xw[offA] : 0.f;
    float xwB = keeper ? g_xw[offB] : 0.f;

    for (int t = 0; t < TT; t++) {
        const int p = t & 1, pn = p ^ 1;

        // Prefetch next step's xw (hidden behind the whole step)
        float nA = 0.f, nB = 0.f;
        if (keeper && t + 1 < TT) {
            nA = g_xw[(size_t)(t + 1) * (BB * HH) + offA];
            nB = g_xw[(size_t)(t + 1) * (BB * HH) + offB];
        }

        // ================= stream A =================
        float sumA = 0.f;
        if (t > 0) {
            mbar_wait_cluster(mb + p * 8, (uint32_t)phA[p]); phA[p] ^= 1;
            const float* hp = hA + p * 1032 + b_l * 516 + ks * 256;
            float ax = 0.f, ay = 0.f, az = 0.f, aw = 0.f;
            #pragma unroll 16
            for (int k4 = 0; k4 < 64; k4++) {
                float4 wv = *(const float4*)(wp + k4 * 4);
                float4 hv = *(const float4*)(hp + k4 * 4);
                ax += wv.x * hv.x;
                ay += wv.y * hv.y;
                az += wv.z * hv.z;
                aw += wv.w * hv.w;
            }
            sumA = (ax + ay) + (az + aw);
            sumA += __shfl_xor_sync(0xffffffffu, sumA, 16);
        }
        float vA = 0.f;
        if (keeper) { vA = fmaxf(xwA + sumA, 0.f); sA[b_l * 68 + h_l] = vA; }
        __syncthreads();   // stage A ready
        if (t < TT - 1) {
            float4 v = *(const float4*)&sA[p_b * 68 + p_j];
            st_cluster_b64(dA[pn],     v.x, v.y);
            st_cluster_b64(dA[pn] + 8, v.z, v.w);
        }

        // ================= stream B (overlaps A's exchange) =================
        float sumB = 0.f;
        if (t > 0) {
            mbar_wait_cluster(mb + 16 + p * 8, (uint32_t)phB[p]); phB[p] ^= 1;
            const float* hp = hB + p * 1032 + b_l * 516 + ks * 256;
            float bx = 0.f, by = 0.f, bz = 0.f, bw = 0.f;
            #pragma unroll 16
            for (int k4 = 0; k4 < 64; k4++) {
                float4 wv = *(const float4*)(wp + k4 * 4);
                float4 hv = *(const float4*)(hp + k4 * 4);
                bx += wv.x * hv.x;
                by += wv.y * hv.y;
                bz += wv.z * hv.z;
                bw += wv.w * hv.w;
            }
            sumB = (bx + by) + (bz + bw);
            sumB += __shfl_xor_sync(0xffffffffu, sumB, 16);
        }
        float vB = 0.f;
        if (keeper) { vB = fmaxf(xwB + sumB, 0.f); sB[b_l * 68 + h_l] = vB; }
        __syncthreads();   // stage B ready
        if (t < TT - 1) {
            float4 v = *(const float4*)&sB[p_b * 68 + p_j];
            st_cluster_b64(dB[pn],     v.x, v.y);
            st_cluster_b64(dB[pn] + 8, v.z, v.w);
            // Make this thread's cluster stores (both streams) release-visible.
            asm volatile("fence.acq_rel.cluster;" ::: "memory");
        }

        // Output stores (off critical path)
        if (keeper) {
            out[(size_t)t * (BB * HH) + offA] = vA;
            out[(size_t)t * (BB * HH) + offB] = vB;
            if (has_hfinal && t == TT - 1) {
                out[(size_t)TT * BB * HH + offA] = vA;
                out[(size_t)TT * BB * HH + offB] = vB;
            }
        }
        xwA = nA; xwB = nB;

        __syncthreads();   // all pushes + fences done CTA-wide
        if (t < TT - 1 && tid < 16) {
            mbar_arrive_pre(remBar[pn]);   // 8 arrives per stream barrier
        }
    }

    asm volatile("barrier.cluster.arrive.aligned;" ::: "memory");
    asm volatile("barrier.cluster.wait.aligned;" ::: "memory");
}

// ---------------------------------------------------------------------------
extern "C" void kernel_launch(void* const* d_in, const int* in_sizes, int n_in,
                              void* d_out, int out_size) {
    const float* x   = (const float*)d_in[0];   // [T,B,I]
    const float* wih = (const float*)d_in[1];   // [H,I]
    const float* whh = (const float*)d_in[2];   // [H,H]
    const float* bih = (const float*)d_in[3];   // [H]
    const float* bhh = (const float*)d_in[4];   // [H]
    float* out = (float*)d_out;

    const int has_hfinal = (out_size >= TT * BB * HH + BB * HH) ? 1 : 0;

    cudaFuncSetAttribute(scan_kernel,
                         cudaFuncAttributeMaxDynamicSharedMemorySize,
                         SM_TOTAL_BYTES);

    dim3 g1(TT * BB / 64, HH / 64);   // (512, 8)
    phase1_kernel<<<g1, 256>>>(x, wih, bih, bhh);

    scan_kernel<<<128, 256, SM_TOTAL_BYTES>>>(whh, out, has_hfinal);
}

// round 13
// speedup vs baseline: 1.0748x; 1.0748x over previous
#include <cuda_runtime.h>
#include <cstdint>

#define TT 512
#define BB 64
#define II 256
#define HH 512

// 64MB scratch for the precomputed input contribution xw[t][b][h]
__device__ float g_xw[TT * BB * HH];

// ---------------------------------------------------------------------------
// Phase 1: g_xw[m][h] = sum_i x[m][i] * W_ih[h][i] + b_ih[h] + b_hh[h]
//   64x64 tiles, BK=32, 256 threads, 4x4 per thread, 2 CTAs/SM.
//   SMEM tiles stored TRANSPOSED (aT[k][m], wT[k][n]) so inner-loop LDS.128
//   reads are 16 distinct contiguous float4 (2-phase, conflict-free).
// ---------------------------------------------------------------------------
__global__ __launch_bounds__(256, 2) void phase1_kernel(
    const float* __restrict__ A,
    const float* __restrict__ W,
    const float* __restrict__ bih,
    const float* __restrict__ bhh)
{
    __shared__ float aT[32][68];
    __shared__ float wT[32][68];

    const int tid = threadIdx.x;
    const int m0 = blockIdx.x * 64;
    const int n0 = blockIdx.y * 64;
    const int r0 = (tid & 15) * 4;
    const int c0 = (tid >> 4) * 4;

    float acc[4][4] = {};

    for (int k0 = 0; k0 < II; k0 += 32) {
        #pragma unroll
        for (int i = 0; i < 2; i++) {
            int idx = tid + i * 256;          // 0..511
            int row = idx >> 3;               // 0..63
            int kc  = (idx & 7) * 4;          // 0..28
            float4 av = *(const float4*)&A[(size_t)(m0 + row) * II + k0 + kc];
            aT[kc + 0][row] = av.x;
            aT[kc + 1][row] = av.y;
            aT[kc + 2][row] = av.z;
            aT[kc + 3][row] = av.w;
            float4 wv = *(const float4*)&W[(size_t)(n0 + row) * II + k0 + kc];
            wT[kc + 0][row] = wv.x;
            wT[kc + 1][row] = wv.y;
            wT[kc + 2][row] = wv.z;
            wT[kc + 3][row] = wv.w;
        }
        __syncthreads();

        #pragma unroll
        for (int k = 0; k < 32; k++) {
            float4 a4 = *(float4*)&aT[k][r0];
            float4 w4 = *(float4*)&wT[k][c0];
            float av[4] = {a4.x, a4.y, a4.z, a4.w};
            float wv[4] = {w4.x, w4.y, w4.z, w4.w};
            #pragma unroll
            for (int i = 0; i < 4; i++)
                #pragma unroll
                for (int j = 0; j < 4; j++)
                    acc[i][j] += av[i] * wv[j];
        }
        __syncthreads();
    }

    float b0 = bih[n0 + c0 + 0] + bhh[n0 + c0 + 0];
    float b1 = bih[n0 + c0 + 1] + bhh[n0 + c0 + 1];
    float b2 = bih[n0 + c0 + 2] + bhh[n0 + c0 + 2];
    float b3 = bih[n0 + c0 + 3] + bhh[n0 + c0 + 3];
    #pragma unroll
    for (int i = 0; i < 4; i++) {
        float4 o;
        o.x = acc[i][0] + b0;
        o.y = acc[i][1] + b1;
        o.z = acc[i][2] + b2;
        o.w = acc[i][3] + b3;
        *(float4*)&g_xw[(size_t)(m0 + r0 + i) * HH + n0 + c0] = o;
    }
}

// ---------------------------------------------------------------------------
// Cluster helpers
// ---------------------------------------------------------------------------
__device__ __forceinline__ uint32_t smem_u32(const void* p) {
    uint32_t a;
    asm("{ .reg .u64 t; cvta.to.shared.u64 t, %1; cvt.u32.u64 %0, t; }"
        : "=r"(a) : "l"(p));
    return a;
}

__device__ __forceinline__ uint32_t mapa_u32(uint32_t laddr, uint32_t rank) {
    uint32_t ra;
    asm("mapa.shared::cluster.u32 %0, %1, %2;" : "=r"(ra) : "r"(laddr), "r"(rank));
    return ra;
}

// 8-byte DSMEM store to a pre-mapa'd remote address.
__device__ __forceinline__ void st_cluster_b64(uint32_t addr, float a, float b) {
    uint64_t v = ((uint64_t)__float_as_uint(b) << 32) | (uint64_t)__float_as_uint(a);
    asm volatile("st.shared::cluster.b64 [%0], %1;" :: "r"(addr), "l"(v) : "memory");
}

// barrier.cluster: arrive has RELEASE semantics (orders our shared::cluster
// stores), wait has ACQUIRE (makes peers' stores visible). One per step.
__device__ __forceinline__ void cluster_sync() {
    asm volatile("barrier.cluster.arrive.aligned;" ::: "memory");
    asm volatile("barrier.cluster.wait.aligned;" ::: "memory");
}

// ---------------------------------------------------------------------------
// Phase 2: cluster scan, 512 threads/CTA, ONE barrier.cluster per step.
//   16 clusters x 8 CTAs. Cluster cid owns batches [4cid, 4cid+4).
//   CTA rank r owns hidden rows [64r, 64r+64); W slice row-major in SMEM.
//   16 warps: warp-group ks (warps 0-7: k in [0,256), warps 8-15: [256,512)),
//   each warp covers 8h x 4b (w-LDS 128B bcast, h-LDS 64B bcast).
//   ks=1 writes partials to psum; ks=0 adds, relu, stages, stores out.
//   Exchange: double-buffered hbuf, pushes via st.shared::cluster,
//   ordering by the barrier.cluster release/acquire. No mbarriers at all.
//
// SMEM layout (floats):
//   [0, 33024)        w_s   [64][516]
//   [33024, 37152)    hbuf  [2][4][516]
//   [37152, 37408)    psum  [256]
//   [37408, 37680)    stage [4][68]
// ---------------------------------------------------------------------------
#define SF_HBUF  33024
#define SF_PSUM  37152
#define SF_STAGE 37408
#define SM_TOTAL_BYTES (37680 * 4)

__global__ void __cluster_dims__(8, 1, 1) __launch_bounds__(512, 1)
scan_kernel(const float* __restrict__ Whh, float* __restrict__ out, int has_hfinal)
{
    extern __shared__ float sm[];
    float* w_s   = sm;
    float* hbuf  = sm + SF_HBUF;
    float* psum  = sm + SF_PSUM;
    float* stage = sm + SF_STAGE;

    const uint32_t base = smem_u32(sm);

    const int tid  = threadIdx.x;
    const int lane = tid & 31;
    const int wrp  = tid >> 5;          // 0..15
    uint32_t r;
    asm("mov.u32 %0, %%cluster_ctarank;" : "=r"(r));
    const int my_r = (int)r;
    const int cid = blockIdx.x >> 3;
    const int b0 = cid * 4;
    const int h0 = my_r * 64;

    // Load W_hh rows [h0, h0+64) row-major into w_s (coalesced, one-time).
    #pragma unroll
    for (int i = 0; i < 16; i++) {
        int idx = tid + i * 512;        // 0..8191 float4 ids
        int row = idx >> 7;
        int kq  = idx & 127;
        *(float4*)&w_s[row * 516 + kq * 4] =
            *(const float4*)&Whh[(size_t)(h0 + row) * HH + kq * 4];
    }
    __syncthreads();
    cluster_sync();   // all CTAs resident & ready before any DSMEM push

    // Compute role: warp = 8h x 4b; warp-group = k-half.
    const int ks   = wrp >> 3;                     // 0..1
    const int h_l  = ((wrp & 7) << 3) | (lane & 7); // 0..63
    const int b_l  = lane >> 3;                    // 0..3
    const bool keeper = (ks == 0);
    const float* wp = w_s + h_l * 516 + ks * 256;
    const int po = b_l * 64 + h_l;                 // psum/stage index
    const size_t off_bh = (size_t)(b0 + b_l) * HH + h0 + h_l;

    // Push role: 64 threads per destination rank; thread covers 16B.
    const int p_dst = tid >> 6;          // 0..7
    const int p_b   = (tid >> 4) & 3;    // 0..3
    const int p_j   = (lane & 15) * 4;   // 0..60
    uint32_t dstA[2];
    #pragma unroll
    for (int pn = 0; pn < 2; pn++) {
        dstA[pn] = mapa_u32(
            base + (uint32_t)(SF_HBUF + pn * 2064 + p_b * 516 + my_r * 64 + p_j) * 4u,
            (uint32_t)p_dst);
    }

    float xw_cur = keeper ? g_xw[off_bh] : 0.f;

    for (int t = 0; t < TT; t++) {
        const int p = t & 1, pn = p ^ 1;

        // Prefetch next step's xw (hidden behind the whole step)
        float xw_next = 0.f;
        if (keeper && t + 1 < TT)
            xw_next = g_xw[(size_t)(t + 1) * (BB * HH) + off_bh];

        // K=256 dot product for this thread's (h,b), k-half ks
        float sum = 0.f;
        if (t > 0) {
            const float* hp = hbuf + p * 2064 + b_l * 516 + ks * 256;
            float ax = 0.f, ay = 0.f, az = 0.f, aw = 0.f;
            #pragma unroll 8
            for (int k4 = 0; k4 < 64; k4++) {
                float4 wv = *(const float4*)(wp + k4 * 4);
                float4 hv = *(const float4*)(hp + k4 * 4);
                ax += wv.x * hv.x;
                ay += wv.y * hv.y;
                az += wv.z * hv.z;
                aw += wv.w * hv.w;
            }
            sum = (ax + ay) + (az + aw);
        }

        if (!keeper) psum[po] = sum;     // ks=1 partial
        __syncthreads();

        if (keeper) {
            float v = fmaxf(xw_cur + sum + ((t > 0) ? psum[po] : 0.f), 0.f);
            stage[b_l * 68 + h_l] = v;
            out[(size_t)t * (BB * HH) + off_bh] = v;
            if (has_hfinal && t == TT - 1)
                out[(size_t)TT * BB * HH + off_bh] = v;
        }
        xw_cur = xw_next;
        __syncthreads();                 // stage complete before pushes

        if (t < TT - 1) {
            // Push my 64h x 4b slice (1KB) to every rank's hbuf[pn]
            float4 v = *(const float4*)&stage[p_b * 68 + p_j];
            st_cluster_b64(dstA[pn],     v.x, v.y);
            st_cluster_b64(dstA[pn] + 8, v.z, v.w);
            // Release (orders pushes) + acquire (peers' pushes visible)
            cluster_sync();
        }
    }

    cluster_sync();   // no CTA exits while peers could still target its SMEM
}

// ---------------------------------------------------------------------------
extern "C" void kernel_launch(void* const* d_in, const int* in_sizes, int n_in,
                              void* d_out, int out_size) {
    const float* x   = (const float*)d_in[0];   // [T,B,I]
    const float* wih = (const float*)d_in[1];   // [H,I]
    const float* whh = (const float*)d_in[2];   // [H,H]
    const float* bih = (const float*)d_in[3];   // [H]
    const float* bhh = (const float*)d_in[4];   // [H]
    float* out = (float*)d_out;

    const int has_hfinal = (out_size >= TT * BB * HH + BB * HH) ? 1 : 0;

    cudaFuncSetAttribute(scan_kernel,
                         cudaFuncAttributeMaxDynamicSharedMemorySize,
                         SM_TOTAL_BYTES);

    dim3 g1(TT * BB / 64, HH / 64);   // (512, 8)
    phase1_kernel<<<g1, 256>>>(x, wih, bih, bhh);

    scan_kernel<<<128, 512, SM_TOTAL_BYTES>>>(whh, out, has_hfinal);
}

// round 17
// speedup vs baseline: 2.0747x; 1.9302x over previous
#include <cuda_runtime.h>
#include <cstdint>

#define TT 512
#define BB 64
#define II 256
#define HH 512

// 64MB scratch for the precomputed input contribution xw[t][b][h]
__device__ float g_xw[TT * BB * HH];
// Double-buffered hidden state, exchanged through L2: [parity][b][520]
__device__ float g_h[2][BB][520];
// One arrival counter per group of 8 CTAs, 128B apart
__device__ unsigned int g_cnt[16][32];

// ---------------------------------------------------------------------------
// Reset group counters (runs before scan on the same stream; graph-capturable)
// ---------------------------------------------------------------------------
__global__ void reset_kernel() {
    if (threadIdx.x < 16) g_cnt[threadIdx.x][0] = 0u;
}

// ---------------------------------------------------------------------------
// Phase 1: g_xw[m][h] = sum_i x[m][i] * W_ih[h][i] + b_ih[h] + b_hh[h]
//   Transposed smem tiles -> conflict-free LDS, 2 CTAs/SM.
// ---------------------------------------------------------------------------
__global__ __launch_bounds__(256, 2) void phase1_kernel(
    const float* __restrict__ A,
    const float* __restrict__ W,
    const float* __restrict__ bih,
    const float* __restrict__ bhh)
{
    __shared__ float aT[32][68];
    __shared__ float wT[32][68];

    const int tid = threadIdx.x;
    const int m0 = blockIdx.x * 64;
    const int n0 = blockIdx.y * 64;
    const int r0 = (tid & 15) * 4;
    const int c0 = (tid >> 4) * 4;

    float acc[4][4] = {};

    for (int k0 = 0; k0 < II; k0 += 32) {
        #pragma unroll
        for (int i = 0; i < 2; i++) {
            int idx = tid + i * 256;
            int row = idx >> 3;
            int kc  = (idx & 7) * 4;
            float4 av = *(const float4*)&A[(size_t)(m0 + row) * II + k0 + kc];
            aT[kc + 0][row] = av.x;
            aT[kc + 1][row] = av.y;
            aT[kc + 2][row] = av.z;
            aT[kc + 3][row] = av.w;
            float4 wv = *(const float4*)&W[(size_t)(n0 + row) * II + k0 + kc];
            wT[kc + 0][row] = wv.x;
            wT[kc + 1][row] = wv.y;
            wT[kc + 2][row] = wv.z;
            wT[kc + 3][row] = wv.w;
        }
        __syncthreads();

        #pragma unroll
        for (int k = 0; k < 32; k++) {
            float4 a4 = *(float4*)&aT[k][r0];
            float4 w4 = *(float4*)&wT[k][c0];
            float av[4] = {a4.x, a4.y, a4.z, a4.w};
            float wv[4] = {w4.x, w4.y, w4.z, w4.w};
            #pragma unroll
            for (int i = 0; i < 4; i++)
                #pragma unroll
                for (int j = 0; j < 4; j++)
                    acc[i][j] += av[i] * wv[j];
        }
        __syncthreads();
    }

    float b0 = bih[n0 + c0 + 0] + bhh[n0 + c0 + 0];
    float b1 = bih[n0 + c0 + 1] + bhh[n0 + c0 + 1];
    float b2 = bih[n0 + c0 + 2] + bhh[n0 + c0 + 2];
    float b3 = bih[n0 + c0 + 3] + bhh[n0 + c0 + 3];
    #pragma unroll
    for (int i = 0; i < 4; i++) {
        float4 o;
        o.x = acc[i][0] + b0;
        o.y = acc[i][1] + b1;
        o.z = acc[i][2] + b2;
        o.w = acc[i][3] + b3;
        *(float4*)&g_xw[(size_t)(m0 + r0 + i) * HH + n0 + c0] = o;
    }
}

// ---------------------------------------------------------------------------
// Phase 2: L2-exchange scan. NO clusters, NO DSMEM, NO mbarriers.
//   128 plain CTAs = 16 independent groups of 8.
//   Group g owns batches [4g, 4g+4); CTA rank r owns h rows [64r, 64r+64),
//   W slice (row-major, 132KB) SMEM-resident.
//   Per step: poll group counter (ld.acquire.gpu) -> stage peers' h from L2
//   into smem -> K=512 dot per thread -> relu -> STG h slice + out ->
//   __syncthreads -> tid0 red.add.release.gpu (fire-and-forget).
//   Counter semantics: value >= 8t  <=>  all 8 CTAs wrote h(t-1) AND finished
//   reading buf[(t-1)&1] -> safe to read h(t-1) and overwrite buf[t&1].
//
// SMEM (floats): w_s [64][516] @0,  hbuf [4][516] @33024  (35088 total)
// ---------------------------------------------------------------------------
#define SF_HBUF 33024
#define SM_TOTAL_BYTES (35088 * 4)

__global__ void __launch_bounds__(256, 1)
scan_kernel(const float* __restrict__ Whh, float* __restrict__ out, int has_hfinal)
{
    extern __shared__ float sm[];
    float* w_s  = sm;
    float* hbuf = sm + SF_HBUF;

    const int tid = threadIdx.x;
    const int grp = blockIdx.x >> 3;   // 0..15
    const int rnk = blockIdx.x & 7;    // 0..7
    const int b0 = grp * 4;
    const int h0 = rnk * 64;

    unsigned int* cnt = &g_cnt[grp][0];

    // Load W_hh rows [h0, h0+64) row-major into w_s (coalesced, one-time).
    #pragma unroll
    for (int i = 0; i < 32; i++) {
        int idx = tid + i * 256;       // 0..8191 float4 ids
        int row = idx >> 7;
        int kq  = idx & 127;
        *(float4*)&w_s[row * 516 + kq * 4] =
            *(const float4*)&Whh[(size_t)(h0 + row) * HH + kq * 4];
    }

    // Compute role: warp = 8h x 4b (w-LDS 128B conflict-free, h-LDS bcast)
    const int h_l = (tid & 7) | ((tid >> 5) << 3);   // 0..63
    const int b_l = (tid >> 3) & 3;                  // 0..3
    const float* wrow = &w_s[h_l * 516];
    const size_t off_bh = (size_t)(b0 + b_l) * HH + h0 + h_l;

    // Stage role: thread loads 2 float4 of the group's 4x512 h slab
    const int s_row = tid >> 7;              // 0..1 (two rows per pass)
    const int s_kc  = (tid & 127) * 4;       // 0..508

    __syncthreads();   // w_s ready

    float xw_cur = g_xw[off_bh];   // t = 0

    for (int t = 0; t < TT; t++) {
        const int pw = t & 1;            // write buffer for h(t)
        const int pr = pw ^ 1;           // read buffer holding h(t-1)

        if (t > 0) {
            // ---- wait: all 8 CTAs arrived for step t-1 ----
            if (tid == 0) {
                const unsigned int want = 8u * (unsigned int)t;
                unsigned int c;
                do {
                    asm volatile("ld.acquire.gpu.global.u32 %0, [%1];"
                                 : "=r"(c) : "l"(cnt) : "memory");
                } while (c < want);
            }
            __syncthreads();

            // ---- stage h(t-1): 4 batches x 512 floats from L2 ----
            #pragma unroll
            for (int j = 0; j < 2; j++) {
                int row = s_row + j * 2;
                *(float4*)&hbuf[row * 516 + s_kc] =
                    *(const float4*)&g_h[pr][b0 + row][s_kc];
            }
            __syncthreads();
        }

        // Prefetch next xw (independent; hidden behind compute)
        float xw_next = 0.f;
        if (t + 1 < TT)
            xw_next = g_xw[(size_t)(t + 1) * (BB * HH) + off_bh];

        // ---- K=512 dot product ----
        float sum = 0.f;
        if (t > 0) {
            const float* hrow = &hbuf[b_l * 516];
            float ax = 0.f, ay = 0.f, az = 0.f, aw = 0.f;
            #pragma unroll 16
            for (int k4 = 0; k4 < 128; k4++) {
                float4 wv = *(const float4*)(wrow + k4 * 4);
                float4 hv = *(const float4*)(hrow + k4 * 4);
                ax += wv.x * hv.x;
                ay += wv.y * hv.y;
                az += wv.z * hv.z;
                aw += wv.w * hv.w;
            }
            sum = (ax + ay) + (az + aw);
        }

        float v = fmaxf(xw_cur + sum, 0.0f);
        xw_cur = xw_next;

        // Publish h(t) + output
        g_h[pw][b0 + b_l][h0 + h_l] = v;
        out[(size_t)t * (BB * HH) + off_bh] = v;
        if (has_hfinal && t == TT - 1)
            out[(size_t)TT * BB * HH + off_bh] = v;

        // ---- arrive: all threads' stores ordered before tid0's release ----
        __syncthreads();
        if (tid == 0) {
            asm volatile("red.add.release.gpu.global.u32 [%0], 1;"
                         :: "l"(cnt) : "memory");
        }
    }
}

// ---------------------------------------------------------------------------
extern "C" void kernel_launch(void* const* d_in, const int* in_sizes, int n_in,
                              void* d_out, int out_size) {
    const float* x   = (const float*)d_in[0];   // [T,B,I]
    const float* wih = (const float*)d_in[1];   // [H,I]
    const float* whh = (const float*)d_in[2];   // [H,H]
    const float* bih = (const float*)d_in[3];   // [H]
    const float* bhh = (const float*)d_in[4];   // [H]
    float* out = (float*)d_out;

    const int has_hfinal = (out_size >= TT * BB * HH + BB * HH) ? 1 : 0;

    cudaFuncSetAttribute(scan_kernel,
                         cudaFuncAttributeMaxDynamicSharedMemorySize,
                         SM_TOTAL_BYTES);

    reset_kernel<<<1, 32>>>();

    dim3 g1(TT * BB / 64, HH / 64);   // (512, 8)
    phase1_kernel<<<g1, 256>>>(x, wih, bih, bhh);

    scan_kernel<<<128, 256, SM_TOTAL_BYTES>>>(whh, out, has_hfinal);
}